// round 7
// baseline (speedup 1.0000x reference)
#include <cuda_runtime.h>
#include <cuda_fp16.h>
#include <math.h>
#include <stdint.h>

#define VCAB 50257
#define EDIM 256
#define HDIM 512
#define BATCH 64
#define SLEN 128
#define TLEN 64
#define TD 63            // decoder steps (T-1)
#define GDIM 2048        // 4*H

// fc GEMM dims (fp16 mma.sync path)
#define KD 1024
#define MPAD 4096
#define NPAD 50432
#define NCHK 16          // KD / 64
#define STGB 32768       // stage bytes: A 16KB + B 16KB

// ---------------- scratch (static device allocations; no cudaMalloc) ----------------
__device__ __align__(16) float g_benc[GDIM];
__device__ __align__(16) float g_bdec[GDIM];
__device__ __align__(16) float g_encX[SLEN * BATCH * EDIM];
__device__ __align__(16) float g_xprojE[(size_t)SLEN * BATCH * GDIM];
__device__ __align__(16) float g_decX[TD * BATCH * EDIM];
__device__ __align__(16) float g_decxp[(size_t)TD * BATCH * GDIM];
__device__ __align__(16) float g_encout[(size_t)BATCH * SLEN * HDIM];
__device__ __align__(16) float g_encWe[(size_t)BATCH * SLEN * HDIM];
__device__ __align__(16) float g_hbuf[2][BATCH * HDIM];
__device__ __align__(16) float g_c[BATCH * HDIM];
__device__ __align__(16) float g_xcat2[2][BATCH * 1024];
// gate-interleaved TRANSPOSED weights: [k][n], n = j*4 + gate (gate order i,f,g,o)
__device__ __align__(16) float g_WencIT[(size_t)HDIM * GDIM];     // [512 k][2048 n]
__device__ __align__(16) float g_WpackIT[(size_t)1024 * GDIM];    // [1024 k][2048 n]
__device__ __align__(16) float g_hwp2[(size_t)16 * BATCH * HDIM]; // hWh partials (16 split-K)
// fp16 operands for the tensor-core fc GEMM (pad rows stay zero: never written)
__device__ __align__(16) __half g_Ahf[(size_t)MPAD * KD];
__device__ __align__(16) __half g_Bhf[(size_t)NPAD * KD];

__device__ __forceinline__ float sigf(float x) { return 1.0f / (1.0f + expf(-x)); }

// ---------------- PTX helpers (compute_103-safe) ----------------
__device__ __forceinline__ uint32_t smem_u32(const void* p) {
    uint32_t a;
    asm("{ .reg .u64 t; cvta.to.shared.u64 t, %1; cvt.u32.u64 %0, t; }" : "=r"(a) : "l"(p));
    return a;
}
__device__ __forceinline__ void cpa16(uint32_t dst, const void* src) {
    asm volatile("cp.async.cg.shared.global [%0], [%1], 16;" :: "r"(dst), "l"(src) : "memory");
}
__device__ __forceinline__ void cpa_commit() { asm volatile("cp.async.commit_group;" ::: "memory"); }
template <int N> __device__ __forceinline__ void cpa_wait() {
    asm volatile("cp.async.wait_group %0;" :: "n"(N) : "memory");
}
#define LDMX4(r, addr) \
    asm volatile("ldmatrix.sync.aligned.m8n8.x4.shared.b16 {%0,%1,%2,%3}, [%4];" \
        : "=r"((r)[0]), "=r"((r)[1]), "=r"((r)[2]), "=r"((r)[3]) : "r"(addr))
__device__ __forceinline__ void mma16816(float* c, const uint32_t* a, uint32_t b0, uint32_t b1) {
    asm volatile("mma.sync.aligned.m16n8k16.row.col.f32.f16.f16.f32 "
        "{%0,%1,%2,%3}, {%4,%5,%6,%7}, {%8,%9}, {%0,%1,%2,%3};"
        : "+f"(c[0]), "+f"(c[1]), "+f"(c[2]), "+f"(c[3])
        : "r"(a[0]), "r"(a[1]), "r"(a[2]), "r"(a[3]), "r"(b0), "r"(b1));
}

// ---------------- setup kernels ----------------
__global__ void k_bias(const float* __restrict__ ebih, const float* __restrict__ ebhh,
                       const float* __restrict__ dbih, const float* __restrict__ dbhh) {
    int j = blockIdx.x * blockDim.x + threadIdx.x;
    if (j < GDIM) {
        g_benc[j] = ebih[j] + ebhh[j];
        g_bdec[j] = dbih[j] + dbhh[j];
    }
}

// interleaved-transposed encoder Whh: g_WencIT[k][j*4+g] = Whh[g*512+j][k]
__global__ void k_wI_enc(const float* __restrict__ Whh) {
    size_t idx = (size_t)blockIdx.x * blockDim.x + threadIdx.x;
    if (idx >= (size_t)HDIM * GDIM) return;
    int k = (int)(idx >> 11);
    int n = (int)(idx & 2047);
    int j = n >> 2, g = n & 3;
    g_WencIT[idx] = Whh[(size_t)(g * 512 + j) * 512 + k];
}

// interleaved-transposed decoder packed weights:
// k<512: dec_Whh[g*512+j][k]; k>=512: dec_Wih[g*512+j][256 + (k-512)]
__global__ void k_wI_dec(const float* __restrict__ dWih, const float* __restrict__ dWhh) {
    size_t idx = (size_t)blockIdx.x * blockDim.x + threadIdx.x;
    if (idx >= (size_t)1024 * GDIM) return;
    int k = (int)(idx >> 11);
    int n = (int)(idx & 2047);
    int j = n >> 2, g = n & 3;
    int row = g * 512 + j;
    g_WpackIT[idx] = (k < 512) ? dWhh[(size_t)row * 512 + k]
                               : dWih[(size_t)row * (EDIM + HDIM) + EDIM + (k - 512)];
}

__global__ void k_gather_enc(const float* __restrict__ emb, const int* __restrict__ src) {
    int m = blockIdx.x;
    int e = threadIdx.x;
    int s = m >> 6, b = m & 63;
    int tok = src[b * SLEN + s];
    g_encX[(size_t)m * EDIM + e] = emb[(size_t)tok * EDIM + e];
}

__global__ void k_gather_dec(const float* __restrict__ emb, const int* __restrict__ trg) {
    int m = blockIdx.x;
    int e = threadIdx.x;
    int t = m >> 6, b = m & 63;
    int tok = trg[b * TLEN + t];
    g_decX[(size_t)m * EDIM + e] = emb[(size_t)tok * EDIM + e];
}

__global__ void k_zero_out(float* __restrict__ out) {
    size_t idx = (size_t)blockIdx.x * blockDim.x + threadIdx.x;
    if (idx >= (size_t)BATCH * VCAB) return;
    size_t b = idx / VCAB, v = idx % VCAB;
    out[b * (size_t)TLEN * VCAB + v] = 0.0f;
}

__global__ void k_zero_hc() {
    int i = blockIdx.x * blockDim.x + threadIdx.x;
    if (i < BATCH * HDIM) { g_hbuf[0][i] = 0.0f; g_c[i] = 0.0f; }
}

// xcat2[0] h-part = encoder final h (SLEN=128 even -> g_hbuf[0])
__global__ void k_init_dec() {
    int i = blockIdx.x * blockDim.x + threadIdx.x;   // 32768
    int b = i >> 9, j = i & 511;
    g_xcat2[0][b * 1024 + j] = g_hbuf[0][b * 512 + j];
}

__global__ void k_convB_h(const float* __restrict__ W) {
    size_t i4 = (size_t)blockIdx.x * blockDim.x + threadIdx.x;
    if (i4 * 4 >= (size_t)VCAB * KD) return;
    float4 v = *reinterpret_cast<const float4*>(W + i4 * 4);
    __half2* dst = reinterpret_cast<__half2*>(g_Bhf + i4 * 4);
    dst[0] = __floats2half2_rn(v.x, v.y);
    dst[1] = __floats2half2_rn(v.z, v.w);
}

// ---------------- fused encoder step: gates GEMM (64m x 16n, K=512) + LSTM ----------------
// grid 128: block owns j-dims [bid*4, bid*4+4) (16 interleaved n-cols = 4 j x 4 gates)
__global__ void __launch_bounds__(256, 1) enc_step(int t) {
    __shared__ float Bs[512 * 17];   // [k][n], padded row 17
    __shared__ float As[16 * 64];    // [k][m]
    __shared__ float gsm[64 * 17];   // gates exchange [m][n]
    const int tid = threadIdx.x, bid = blockIdx.x;
    const int n0 = bid * 16;
    const int tx = tid & 15, ty = tid >> 4;
    const int lr = tid >> 2, lk = (tid & 3) << 2;

    // preload weights once (coalesced: 64B row segments)
    {
        int n = tid & 15, kq = tid >> 4;
        for (int k = kq; k < 512; k += 16)
            Bs[k * 17 + n] = g_WencIT[(size_t)k * GDIM + n0 + n];
    }
    const float* hcur = g_hbuf[t & 1];
    float acc0 = 0.f, acc1 = 0.f, acc2 = 0.f, acc3 = 0.f;
    __syncthreads();

    for (int k0 = 0; k0 < 512; k0 += 16) {
        float4 av = *reinterpret_cast<const float4*>(hcur + lr * 512 + k0 + lk);
        __syncthreads();
        As[(lk + 0) * 64 + lr] = av.x;
        As[(lk + 1) * 64 + lr] = av.y;
        As[(lk + 2) * 64 + lr] = av.z;
        As[(lk + 3) * 64 + lr] = av.w;
        __syncthreads();
#pragma unroll
        for (int kk = 0; kk < 16; kk++) {
            float b = Bs[(k0 + kk) * 17 + tx];
            float4 a = *reinterpret_cast<const float4*>(&As[kk * 64 + (ty << 2)]);
            acc0 += a.x * b; acc1 += a.y * b; acc2 += a.z * b; acc3 += a.w * b;
        }
    }
    __syncthreads();
    gsm[((ty << 2) + 0) * 17 + tx] = acc0;
    gsm[((ty << 2) + 1) * 17 + tx] = acc1;
    gsm[((ty << 2) + 2) * 17 + tx] = acc2;
    gsm[((ty << 2) + 3) * 17 + tx] = acc3;
    __syncthreads();

    // LSTM: thread -> (b, jloc); gates at gsm[b][jloc*4 + {i,f,g,o}]
    const int b = tid & 63, jloc = tid >> 6;
    const int jd = bid * 4 + jloc;
    size_t xb = ((size_t)t * 64 + b) * GDIM;
    float gi = gsm[b * 17 + jloc * 4 + 0] + g_xprojE[xb + jd];
    float gf = gsm[b * 17 + jloc * 4 + 1] + g_xprojE[xb + 512 + jd];
    float gg = gsm[b * 17 + jloc * 4 + 2] + g_xprojE[xb + 1024 + jd];
    float go = gsm[b * 17 + jloc * 4 + 3] + g_xprojE[xb + 1536 + jd];
    int ci = b * 512 + jd;
    float cc = sigf(gf) * g_c[ci] + sigf(gi) * tanhf(gg);
    float hh = sigf(go) * tanhf(cc);
    g_c[ci] = cc;
    g_hbuf[(t + 1) & 1][ci] = hh;
    g_encout[((size_t)b * SLEN + t) * 512 + jd] = hh;
}

// ---------------- decoder hWh split-K GEMM: g_hwp2[kz][64][512] ----------------
// grid (8 nt, 16 kz), Kc=32; A = xcat2[t&1] h-part (lda 1024), B = attn_W (ldb 1024)
__global__ void __launch_bounds__(256, 1) dec_hwh(const float* __restrict__ attnW, int t) {
    __shared__ __align__(16) float As[16 * 64];
    __shared__ __align__(16) float Bs2[16 * 64];
    const int tid = threadIdx.x;
    const int n0 = blockIdx.x * 64;
    const int kz = blockIdx.y;
    const int kbeg = kz * 32;
    const int tx = tid & 15, ty = tid >> 4;
    const int lr = tid >> 2, lk = (tid & 3) << 2;
    const float* A = g_xcat2[t & 1];

    float acc[4][4];
#pragma unroll
    for (int i = 0; i < 4; i++)
#pragma unroll
        for (int j = 0; j < 4; j++) acc[i][j] = 0.0f;

    for (int k0 = kbeg; k0 < kbeg + 32; k0 += 16) {
        float4 av = *reinterpret_cast<const float4*>(A + lr * 1024 + k0 + lk);
        float4 bv = *reinterpret_cast<const float4*>(attnW + (size_t)(n0 + lr) * 1024 + k0 + lk);
        __syncthreads();
        As[(lk + 0) * 64 + lr] = av.x; As[(lk + 1) * 64 + lr] = av.y;
        As[(lk + 2) * 64 + lr] = av.z; As[(lk + 3) * 64 + lr] = av.w;
        Bs2[(lk + 0) * 64 + lr] = bv.x; Bs2[(lk + 1) * 64 + lr] = bv.y;
        Bs2[(lk + 2) * 64 + lr] = bv.z; Bs2[(lk + 3) * 64 + lr] = bv.w;
        __syncthreads();
#pragma unroll
        for (int kk = 0; kk < 16; kk++) {
            float4 a = *reinterpret_cast<const float4*>(&As[kk * 64 + (ty << 2)]);
            float4 w = *reinterpret_cast<const float4*>(&Bs2[kk * 64 + (tx << 2)]);
            float ar[4] = {a.x, a.y, a.z, a.w};
            float wr[4] = {w.x, w.y, w.z, w.w};
#pragma unroll
            for (int i = 0; i < 4; i++)
#pragma unroll
                for (int j = 0; j < 4; j++) acc[i][j] += ar[i] * wr[j];
        }
        __syncthreads();
    }
#pragma unroll
    for (int i = 0; i < 4; i++) {
        int m = (ty << 2) + i;
        float4 v = make_float4(acc[i][0], acc[i][1], acc[i][2], acc[i][3]);
        *reinterpret_cast<float4*>(&g_hwp2[((size_t)kz * 64 + m) * 512 + n0 + (tx << 2)]) = v;
    }
}

// ---------------- decoder attention: sum partials + scores + softmax + context ----------------
__global__ void __launch_bounds__(256, 1) k_attn(const float* __restrict__ vw, int t) {
    __shared__ float hwhs[512];
    __shared__ float vws[512];
    __shared__ float sc[128];
    __shared__ float red[128];
    const int bb = blockIdx.x;
    const int tid = threadIdx.x;
    const int cur = t & 1;

    for (int i = tid; i < 512; i += 256) {
        float s = 0.0f;
#pragma unroll
        for (int kz = 0; kz < 16; kz++) s += g_hwp2[((size_t)kz * 64 + bb) * 512 + i];
        hwhs[i] = s;
        vws[i] = vw[i];
    }
    __syncthreads();
    int warp = tid >> 5, lane = tid & 31;
    for (int s = warp; s < SLEN; s += 8) {
        const float* we = &g_encWe[((size_t)bb * SLEN + s) * 512];
        float a = 0.0f;
        for (int j = lane; j < 512; j += 32)
            a += tanhf(hwhs[j] + we[j]) * vws[j];
#pragma unroll
        for (int o = 16; o > 0; o >>= 1) a += __shfl_xor_sync(0xffffffffu, a, o);
        if (lane == 0) sc[s] = a;
    }
    __syncthreads();
    if (tid < SLEN) red[tid] = sc[tid];
    __syncthreads();
    for (int o = 64; o > 0; o >>= 1) {
        if (tid < o) red[tid] = fmaxf(red[tid], red[tid + o]);
        __syncthreads();
    }
    float mx = red[0];
    __syncthreads();
    float e = 0.0f;
    if (tid < SLEN) { e = expf(sc[tid] - mx); red[tid] = e; }
    __syncthreads();
    for (int o = 64; o > 0; o >>= 1) {
        if (tid < o) red[tid] += red[tid + o];
        __syncthreads();
    }
    float inv = 1.0f / red[0];
    __syncthreads();
    if (tid < SLEN) sc[tid] = e * inv;
    __syncthreads();

    float c0 = 0.0f, c1 = 0.0f;
    const float* eo = &g_encout[(size_t)bb * SLEN * 512];
    for (int s = 0; s < SLEN; s++) {
        float w = sc[s];
        c0 += w * eo[s * 512 + tid];
        c1 += w * eo[s * 512 + tid + 256];
    }
    g_xcat2[cur][bb * 1024 + 512 + tid] = c0;
    g_xcat2[cur][bb * 1024 + 512 + tid + 256] = c1;
    size_t ma = ((size_t)t * 64 + bb) * 1024;
    g_Ahf[ma + 512 + tid] = __float2half(c0);
    g_Ahf[ma + 512 + tid + 256] = __float2half(c1);
}

// ---------------- fused decoder gates step: GEMM (64m x 16n, K=1024) + LSTM ----------------
// grid 128; writes h to xcat2[next] + fp16 fc A-matrix
__global__ void __launch_bounds__(256, 1) dec_gates(int t) {
    extern __shared__ float sg[];
    float* Bs = sg;                    // [1024][17]
    float* As = Bs + 1024 * 17;        // [16][64]
    float* gsm = As + 16 * 64;         // [64][17]
    const int tid = threadIdx.x, bid = blockIdx.x;
    const int n0 = bid * 16;
    const int tx = tid & 15, ty = tid >> 4;
    const int lr = tid >> 2, lk = (tid & 3) << 2;

    {
        int n = tid & 15, kq = tid >> 4;
        for (int k = kq; k < 1024; k += 16)
            Bs[k * 17 + n] = g_WpackIT[(size_t)k * GDIM + n0 + n];
    }
    const float* xc = g_xcat2[t & 1];
    float acc0 = 0.f, acc1 = 0.f, acc2 = 0.f, acc3 = 0.f;
    __syncthreads();

    for (int k0 = 0; k0 < 1024; k0 += 16) {
        float4 av = *reinterpret_cast<const float4*>(xc + lr * 1024 + k0 + lk);
        __syncthreads();
        As[(lk + 0) * 64 + lr] = av.x;
        As[(lk + 1) * 64 + lr] = av.y;
        As[(lk + 2) * 64 + lr] = av.z;
        As[(lk + 3) * 64 + lr] = av.w;
        __syncthreads();
#pragma unroll
        for (int kk = 0; kk < 16; kk++) {
            float b = Bs[(k0 + kk) * 17 + tx];
            float4 a = *reinterpret_cast<const float4*>(&As[kk * 64 + (ty << 2)]);
            acc0 += a.x * b; acc1 += a.y * b; acc2 += a.z * b; acc3 += a.w * b;
        }
    }
    __syncthreads();
    gsm[((ty << 2) + 0) * 17 + tx] = acc0;
    gsm[((ty << 2) + 1) * 17 + tx] = acc1;
    gsm[((ty << 2) + 2) * 17 + tx] = acc2;
    gsm[((ty << 2) + 3) * 17 + tx] = acc3;
    __syncthreads();

    const int b = tid & 63, jloc = tid >> 6;
    const int jd = bid * 4 + jloc;
    size_t xb = ((size_t)t * 64 + b) * GDIM;
    float gi = gsm[b * 17 + jloc * 4 + 0] + g_decxp[xb + jd];
    float gf = gsm[b * 17 + jloc * 4 + 1] + g_decxp[xb + 512 + jd];
    float gg = gsm[b * 17 + jloc * 4 + 2] + g_decxp[xb + 1024 + jd];
    float go = gsm[b * 17 + jloc * 4 + 3] + g_decxp[xb + 1536 + jd];
    int ci = b * 512 + jd;
    float cc = sigf(gf) * g_c[ci] + sigf(gi) * tanhf(gg);
    float hh = sigf(go) * tanhf(cc);
    g_c[ci] = cc;
    g_xcat2[(t + 1) & 1][b * 1024 + jd] = hh;
    g_Ahf[((size_t)t * 64 + b) * 1024 + jd] = __float2half(hh);
}

// ---------------- fp16 tensor-core fc GEMM (mma.sync) ----------------
__global__ void __launch_bounds__(256, 1) hgemm_fc(const float* __restrict__ fc_b,
                                                   float* __restrict__ out) {
    extern __shared__ char smc[];
    const uint32_t sbase = smem_u32(smc);
    const int tid = threadIdx.x;
    const int wid = tid >> 5, lane = tid & 31;
    const int m0 = blockIdx.x * 128;
    const int n0 = blockIdx.y * 128;
    const int wm = wid >> 2;
    const int wn = wid & 3;

    const char* Ag = (const char*)g_Ahf + (size_t)m0 * (KD * 2);
    const char* Bg = (const char*)g_Bhf + (size_t)n0 * (KD * 2);

    float acc[4][4][4];
#pragma unroll
    for (int i = 0; i < 4; i++)
#pragma unroll
        for (int j = 0; j < 4; j++)
#pragma unroll
            for (int r = 0; r < 4; r++) acc[i][j][r] = 0.0f;

    auto load_chunk = [&](int kc, int slot) {
        uint32_t st = sbase + (uint32_t)slot * STGB;
#pragma unroll
        for (int i = 0; i < 8; i++) {
            int idx = tid + (i << 8);
            int isB = idx >> 10;
            int r = (idx & 1023) >> 3;
            int seg = idx & 7;
            uint32_t dst = st + (isB ? 16384u : 0u) + (uint32_t)(r << 7)
                         + (uint32_t)(((seg ^ (r & 7)) << 4));
            const char* src = (isB ? Bg : Ag) + (size_t)r * (KD * 2) + (size_t)kc * 128 + (seg << 4);
            cpa16(dst, src);
        }
        cpa_commit();
    };

    const int g = lane >> 3, lr = lane & 7;

    auto compute = [&](int slot) {
        uint32_t Abase = sbase + (uint32_t)slot * STGB;
        uint32_t Bbase = Abase + 16384u;
#pragma unroll
        for (int ks = 0; ks < 4; ks++) {
            uint32_t afr[4][4];
#pragma unroll
            for (int mt = 0; mt < 4; mt++) {
                int row = wm * 64 + mt * 16 + (g & 1) * 8 + lr;
                int kseg = ks * 2 + (g >> 1);
                uint32_t addr = Abase + (uint32_t)(row << 7) + (uint32_t)(((kseg ^ (row & 7)) << 4));
                LDMX4(afr[mt], addr);
            }
            uint32_t bfr[2][4];
#pragma unroll
            for (int np = 0; np < 2; np++) {
                int row = wn * 32 + np * 16 + (g >> 1) * 8 + lr;
                int kseg = ks * 2 + (g & 1);
                uint32_t addr = Bbase + (uint32_t)(row << 7) + (uint32_t)(((kseg ^ (row & 7)) << 4));
                LDMX4(bfr[np], addr);
            }
#pragma unroll
            for (int mt = 0; mt < 4; mt++)
#pragma unroll
                for (int nt = 0; nt < 4; nt++) {
                    const uint32_t* bp = &bfr[nt >> 1][(nt & 1) * 2];
                    mma16816(acc[mt][nt], afr[mt], bp[0], bp[1]);
                }
        }
    };

    load_chunk(0, 0);
    load_chunk(1, 1);
    for (int i = 0; i < NCHK; i++) {
        if (i + 1 < NCHK) cpa_wait<1>(); else cpa_wait<0>();
        __syncthreads();
        if (i + 2 < NCHK) load_chunk(i + 2, (i + 2) % 3);
        compute(i % 3);
    }

    const int quad = lane >> 2, tq = lane & 3;
#pragma unroll
    for (int mt = 0; mt < 4; mt++) {
        int mr0 = m0 + wm * 64 + mt * 16 + quad;
#pragma unroll
        for (int half = 0; half < 2; half++) {
            int m = mr0 + half * 8;
            if (m >= TD * BATCH) continue;
            int bb = m & 63, tt = m >> 6;
            float* orow = out + ((size_t)bb * TLEN + (tt + 1)) * VCAB;
#pragma unroll
            for (int nt = 0; nt < 4; nt++) {
                int n = n0 + wn * 32 + nt * 8 + tq * 2;
                float v0 = acc[mt][nt][half * 2 + 0];
                float v1 = acc[mt][nt][half * 2 + 1];
                if (n < VCAB)     orow[n]     = v0 + fc_b[n];
                if (n + 1 < VCAB) orow[n + 1] = v1 + fc_b[n + 1];
            }
        }
    }
}

// ---------------- generic tiled SGEMM: C[M,N] = A[M,K] @ B[N,K]^T + bias ----------------
__global__ void sgemm64(int M, int N, int K,
                        int asel, int lda,
                        const float* __restrict__ Bp, int ldb,
                        int csel, int ldc,
                        int bsel, const float* __restrict__ biasp) {
    const float* A = (asel == 0) ? g_encX : (asel == 1) ? g_decX : g_encout;
    float* C = (csel == 0) ? g_xprojE : (csel == 1) ? g_decxp : g_encWe;
    const float* bias = (bsel == 0) ? g_benc : (bsel == 1) ? g_bdec : biasp;

    __shared__ __align__(16) float As[16][64];
    __shared__ __align__(16) float Bs[16][64];

    const int tid = threadIdx.x;
    const int tx = tid & 15, ty = tid >> 4;
    const int m0 = blockIdx.y * 64, n0 = blockIdx.x * 64;
    const int lr = tid >> 2;
    const int lk = (tid & 3) << 2;

    float acc[4][4];
#pragma unroll
    for (int i = 0; i < 4; i++)
#pragma unroll
        for (int j = 0; j < 4; j++) acc[i][j] = 0.0f;

    const bool brow_ok = (n0 + lr) < N;
    const float* Arow = A + (size_t)(m0 + lr) * lda;
    const float* Brow = Bp + (size_t)(n0 + lr) * ldb;

    for (int k0 = 0; k0 < K; k0 += 16) {
        float4 av = *reinterpret_cast<const float4*>(Arow + k0 + lk);
        float4 bv = make_float4(0.f, 0.f, 0.f, 0.f);
        if (brow_ok) bv = *reinterpret_cast<const float4*>(Brow + k0 + lk);
        As[lk + 0][lr] = av.x; As[lk + 1][lr] = av.y; As[lk + 2][lr] = av.z; As[lk + 3][lr] = av.w;
        Bs[lk + 0][lr] = bv.x; Bs[lk + 1][lr] = bv.y; Bs[lk + 2][lr] = bv.z; Bs[lk + 3][lr] = bv.w;
        __syncthreads();
#pragma unroll
        for (int kk = 0; kk < 16; kk++) {
            float4 a = *reinterpret_cast<const float4*>(&As[kk][ty << 2]);
            float4 b = *reinterpret_cast<const float4*>(&Bs[kk][tx << 2]);
            float ar[4] = {a.x, a.y, a.z, a.w};
            float br[4] = {b.x, b.y, b.z, b.w};
#pragma unroll
            for (int i = 0; i < 4; i++)
#pragma unroll
                for (int j = 0; j < 4; j++) acc[i][j] += ar[i] * br[j];
        }
        __syncthreads();
    }

#pragma unroll
    for (int i = 0; i < 4; i++) {
        int m = m0 + (ty << 2) + i;
#pragma unroll
        for (int j = 0; j < 4; j++) {
            int n = n0 + (tx << 2) + j;
            if (n < N) C[(size_t)m * ldc + n] = acc[i][j] + bias[n];
        }
    }
}

// ---------------- host driver ----------------
extern "C" void kernel_launch(void* const* d_in, const int* in_sizes, int n_in,
                              void* d_out, int out_size) {
    const int*   src     = (const int*)  d_in[0];
    const int*   trg     = (const int*)  d_in[1];
    const float* enc_emb = (const float*)d_in[2];
    const float* enc_Wih = (const float*)d_in[3];
    const float* enc_Whh = (const float*)d_in[4];
    const float* enc_bih = (const float*)d_in[5];
    const float* enc_bhh = (const float*)d_in[6];
    const float* dec_emb = (const float*)d_in[7];
    const float* dec_Wih = (const float*)d_in[8];
    const float* dec_Whh = (const float*)d_in[9];
    const float* dec_bih = (const float*)d_in[10];
    const float* dec_bhh = (const float*)d_in[11];
    const float* attn_W  = (const float*)d_in[12];
    const float* attn_b  = (const float*)d_in[13];
    const float* v_w     = (const float*)d_in[14];
    const float* fc_W    = (const float*)d_in[15];
    const float* fc_b    = (const float*)d_in[16];
    float* out = (float*)d_out;
    (void)in_sizes; (void)n_in; (void)out_size;

    const int DG_SMEM = (1024 * 17 + 16 * 64 + 64 * 17) * 4;   // 78080
    cudaFuncSetAttribute(hgemm_fc, cudaFuncAttributeMaxDynamicSharedMemorySize, 3 * STGB);
    cudaFuncSetAttribute(dec_gates, cudaFuncAttributeMaxDynamicSharedMemorySize, DG_SMEM);

    // setup
    k_bias<<<8, 256>>>(enc_bih, enc_bhh, dec_bih, dec_bhh);
    k_wI_enc<<<(int)(((size_t)HDIM * GDIM + 255) / 256), 256>>>(enc_Whh);
    k_wI_dec<<<(int)(((size_t)1024 * GDIM + 255) / 256), 256>>>(dec_Wih, dec_Whh);
    k_gather_enc<<<SLEN * BATCH, EDIM>>>(enc_emb, src);
    k_gather_dec<<<TD * BATCH, EDIM>>>(dec_emb, trg);
    k_zero_out<<<(int)(((size_t)BATCH * VCAB + 255) / 256), 256>>>(out);
    k_zero_hc<<<(BATCH * HDIM + 255) / 256, 256>>>();
    k_convB_h<<<(int)(((size_t)VCAB * KD / 4 + 255) / 256), 256>>>(fc_W);

    // batched input projections (fp32)
    sgemm64<<<dim3(GDIM / 64, (SLEN * BATCH) / 64), 256>>>(
        SLEN * BATCH, GDIM, EDIM, 0, EDIM, enc_Wih, EDIM, 0, GDIM, 0, nullptr);
    sgemm64<<<dim3(GDIM / 64, (TD * BATCH) / 64), 256>>>(
        TD * BATCH, GDIM, EDIM, 1, EDIM, dec_Wih, EDIM + HDIM, 1, GDIM, 1, nullptr);

    // encoder: ONE fused kernel per step
    for (int t = 0; t < SLEN; t++)
        enc_step<<<128, 256>>>(t);

    // encWe = enc_out @ attn_W[:, H:]^T + attn_b
    sgemm64<<<dim3(HDIM / 64, (BATCH * SLEN) / 64), 256>>>(
        BATCH * SLEN, HDIM, HDIM, 2, HDIM, attn_W + HDIM, 2 * HDIM, 2, HDIM, 2, attn_b);

    k_init_dec<<<128, 256>>>();

    // decoder: THREE kernels per step
    for (int t = 0; t < TD; t++) {
        dec_hwh<<<dim3(8, 16), 256>>>(attn_W, t);
        k_attn<<<64, 256>>>(v_w, t);
        dec_gates<<<128, 256, DG_SMEM>>>(t);
    }

    // tensor-core fc GEMM
    hgemm_fc<<<dim3(MPAD / 128, NPAD / 128), 256, 3 * STGB>>>(fc_b, out);
}

// round 8
// speedup vs baseline: 1.6705x; 1.6705x over previous
#include <cuda_runtime.h>
#include <cuda_fp16.h>
#include <math.h>
#include <stdint.h>

#define VCAB 50257
#define EDIM 256
#define HDIM 512
#define BATCH 64
#define SLEN 128
#define TLEN 64
#define TD 63            // decoder steps (T-1)
#define GDIM 2048        // 4*H

// fc GEMM dims (fp16 mma.sync path)
#define KD 1024
#define MPAD 4096
#define NPAD 50432
#define NCHK 16          // KD / 64
#define STGB 32768       // stage bytes: A 16KB + B 16KB

// ---------------- scratch (static device allocations; no cudaMalloc) ----------------
__device__ __align__(16) float g_benc[GDIM];
__device__ __align__(16) float g_bdec[GDIM];
__device__ __align__(16) float g_encX[SLEN * BATCH * EDIM];
__device__ __align__(16) float g_xprojE[(size_t)SLEN * BATCH * GDIM];
__device__ __align__(16) float g_decX[TD * BATCH * EDIM];
__device__ __align__(16) float g_decxp[(size_t)TD * BATCH * GDIM];
__device__ __align__(16) float g_encout[(size_t)BATCH * SLEN * HDIM];
__device__ __align__(16) float g_encWe[(size_t)BATCH * SLEN * HDIM];
__device__ __align__(16) float g_c[BATCH * HDIM];
__device__ __align__(16) float g_hwh[BATCH * HDIM];                 // fp32 hWh (direct store)
// fp16 recurrent state
__device__ __align__(16) __half g_eh16[2][BATCH * HDIM];            // encoder h (double buf)
__device__ __align__(16) __half g_xh16[2][BATCH * 1024];            // decoder [h | ctx]
// fp16 gate-interleaved weights: row n = j*4 + gate (i,f,g,o), cols = k
__device__ __align__(16) __half g_We16[(size_t)GDIM * HDIM];        // enc Whh   [2048][512]
__device__ __align__(16) __half g_Wd16[(size_t)GDIM * 1024];        // dec packed [2048][1024]
__device__ __align__(16) __half g_Wh16[(size_t)HDIM * HDIM];        // attn Wh   [512][512]
// fp16 operands for the tensor-core fc GEMM (pad rows stay zero: never written)
__device__ __align__(16) __half g_Ahf[(size_t)MPAD * KD];
__device__ __align__(16) __half g_Bhf[(size_t)NPAD * KD];

__device__ __forceinline__ float sigf(float x) { return 1.0f / (1.0f + expf(-x)); }

// ---------------- PTX helpers (compute_103-safe) ----------------
__device__ __forceinline__ uint32_t smem_u32(const void* p) {
    uint32_t a;
    asm("{ .reg .u64 t; cvta.to.shared.u64 t, %1; cvt.u32.u64 %0, t; }" : "=r"(a) : "l"(p));
    return a;
}
__device__ __forceinline__ void cpa16(uint32_t dst, const void* src) {
    asm volatile("cp.async.cg.shared.global [%0], [%1], 16;" :: "r"(dst), "l"(src) : "memory");
}
__device__ __forceinline__ void cpa_commit() { asm volatile("cp.async.commit_group;" ::: "memory"); }
template <int N> __device__ __forceinline__ void cpa_wait() {
    asm volatile("cp.async.wait_group %0;" :: "n"(N) : "memory");
}
#define LDMX4(r, addr) \
    asm volatile("ldmatrix.sync.aligned.m8n8.x4.shared.b16 {%0,%1,%2,%3}, [%4];" \
        : "=r"((r)[0]), "=r"((r)[1]), "=r"((r)[2]), "=r"((r)[3]) : "r"(addr))
__device__ __forceinline__ void mma16816(float* c, const uint32_t* a, uint32_t b0, uint32_t b1) {
    asm volatile("mma.sync.aligned.m16n8k16.row.col.f32.f16.f16.f32 "
        "{%0,%1,%2,%3}, {%4,%5,%6,%7}, {%8,%9}, {%0,%1,%2,%3};"
        : "+f"(c[0]), "+f"(c[1]), "+f"(c[2]), "+f"(c[3])
        : "r"(a[0]), "r"(a[1]), "r"(a[2]), "r"(a[3]), "r"(b0), "r"(b1));
}

// ---------------- setup kernels ----------------
__global__ void k_bias(const float* __restrict__ ebih, const float* __restrict__ ebhh,
                       const float* __restrict__ dbih, const float* __restrict__ dbhh) {
    int j = blockIdx.x * blockDim.x + threadIdx.x;
    if (j < GDIM) {
        g_benc[j] = ebih[j] + ebhh[j];
        g_bdec[j] = dbih[j] + dbhh[j];
    }
}

// enc Whh -> fp16 gate-interleaved [n=j*4+g][k]
__global__ void k_w16_enc(const float* __restrict__ Whh) {
    size_t idx = (size_t)blockIdx.x * blockDim.x + threadIdx.x;
    if (idx >= (size_t)GDIM * HDIM) return;
    int n = (int)(idx >> 9);
    int k = (int)(idx & 511);
    int j = n >> 2, g = n & 3;
    g_We16[idx] = __float2half(Whh[(size_t)(g * 512 + j) * 512 + k]);
}

// dec packed [Whh | Wih_ctx] -> fp16 gate-interleaved [n][k=0..1023]
__global__ void k_w16_dec(const float* __restrict__ dWih, const float* __restrict__ dWhh) {
    size_t idx = (size_t)blockIdx.x * blockDim.x + threadIdx.x;
    if (idx >= (size_t)GDIM * 1024) return;
    int n = (int)(idx >> 10);
    int k = (int)(idx & 1023);
    int j = n >> 2, g = n & 3;
    int row = g * 512 + j;
    float v = (k < 512) ? dWhh[(size_t)row * 512 + k]
                        : dWih[(size_t)row * (EDIM + HDIM) + EDIM + (k - 512)];
    g_Wd16[idx] = __float2half(v);
}

// attn_W[:, :512] -> fp16 [n][k]
__global__ void k_w16_wh(const float* __restrict__ attnW) {
    size_t idx = (size_t)blockIdx.x * blockDim.x + threadIdx.x;
    if (idx >= (size_t)HDIM * HDIM) return;
    int n = (int)(idx >> 9);
    int k = (int)(idx & 511);
    g_Wh16[idx] = __float2half(attnW[(size_t)n * 1024 + k]);
}

__global__ void k_gather_enc(const float* __restrict__ emb, const int* __restrict__ src) {
    int m = blockIdx.x;
    int e = threadIdx.x;
    int s = m >> 6, b = m & 63;
    int tok = src[b * SLEN + s];
    g_encX[(size_t)m * EDIM + e] = emb[(size_t)tok * EDIM + e];
}

__global__ void k_gather_dec(const float* __restrict__ emb, const int* __restrict__ trg) {
    int m = blockIdx.x;
    int e = threadIdx.x;
    int t = m >> 6, b = m & 63;
    int tok = trg[b * TLEN + t];
    g_decX[(size_t)m * EDIM + e] = emb[(size_t)tok * EDIM + e];
}

__global__ void k_zero_out(float* __restrict__ out) {
    size_t idx = (size_t)blockIdx.x * blockDim.x + threadIdx.x;
    if (idx >= (size_t)BATCH * VCAB) return;
    size_t b = idx / VCAB, v = idx % VCAB;
    out[b * (size_t)TLEN * VCAB + v] = 0.0f;
}

__global__ void k_zero_state() {
    int i = blockIdx.x * blockDim.x + threadIdx.x;
    if (i < BATCH * HDIM) {
        g_eh16[0][i] = __float2half(0.0f);
        g_c[i] = 0.0f;
    }
}

// decoder xcat[0] h-part = encoder final h (SLEN=128 even -> g_eh16[0])
__global__ void k_init_dec() {
    int i = blockIdx.x * blockDim.x + threadIdx.x;   // 32768
    int b = i >> 9, j = i & 511;
    g_xh16[0][b * 1024 + j] = g_eh16[0][b * 512 + j];
}

__global__ void k_convB_h(const float* __restrict__ W) {
    size_t i4 = (size_t)blockIdx.x * blockDim.x + threadIdx.x;
    if (i4 * 4 >= (size_t)VCAB * KD) return;
    float4 v = *reinterpret_cast<const float4*>(W + i4 * 4);
    __half2* dst = reinterpret_cast<__half2*>(g_Bhf + i4 * 4);
    dst[0] = __floats2half2_rn(v.x, v.y);
    dst[1] = __floats2half2_rn(v.z, v.w);
}

// ============ shared fp16 GEMM tile machinery (mirrors proven hgemm_fc) ============
// smem layout per chunk kc (64 k-halves): A: 64 rows x 128B at Aoff+kc*8192;
// B: 32 rows x 128B at Boff+kc*4096. XOR-8 seg swizzle identical to hgemm_fc.

// loads A[64 x K] and B-slice[32 x K] (rows n0..n0+31) into smem, fp16
template <int NCH>
__device__ __forceinline__ void load_AB16(uint32_t Ab, uint32_t Bb,
                                          const __half* __restrict__ Aglob, int apitchB,
                                          const __half* __restrict__ Bglob, int bpitchB,
                                          int n0, int tid) {
    for (int i = tid; i < 64 * 8 * NCH; i += 256) {
        int kc = i >> 9, rem = i & 511;
        int r = rem >> 3, s = rem & 7;
        uint32_t dst = Ab + kc * 8192 + (r << 7) + (((s ^ (r & 7)) << 4));
        const char* src = (const char*)Aglob + (size_t)r * apitchB + kc * 128 + (s << 4);
        cpa16(dst, src);
    }
    for (int i = tid; i < 32 * 8 * NCH; i += 256) {
        int kc = i >> 8, rem = i & 255;
        int r = rem >> 3, s = rem & 7;
        uint32_t dst = Bb + kc * 4096 + (r << 7) + (((s ^ (r & 7)) << 4));
        const char* src = (const char*)Bglob + (size_t)(n0 + r) * bpitchB + kc * 128 + (s << 4);
        cpa16(dst, src);
    }
    cpa_commit();
    cpa_wait<0>();
    __syncthreads();
}

// computes 64x32 tile: warp (wm 0..3, wn 0..1) -> 16m x 16n; acc[2][4]
template <int NCH>
__device__ __forceinline__ void mma_64x32(uint32_t Ab, uint32_t Bb, int lane, int wm, int wn,
                                          float acc[2][4]) {
    const int g = lane >> 3, lr = lane & 7;
    for (int kc = 0; kc < NCH; kc++) {
#pragma unroll
        for (int ks = 0; ks < 4; ks++) {
            uint32_t afr[4], bfr[4];
            {
                int row = wm * 16 + (g & 1) * 8 + lr;
                int kseg = ks * 2 + (g >> 1);
                uint32_t addr = Ab + kc * 8192 + (row << 7) + (((kseg ^ (row & 7)) << 4));
                LDMX4(afr, addr);
            }
            {
                int row = wn * 16 + (g >> 1) * 8 + lr;
                int kseg = ks * 2 + (g & 1);
                uint32_t addr = Bb + kc * 4096 + (row << 7) + (((kseg ^ (row & 7)) << 4));
                LDMX4(bfr, addr);
            }
            mma16816(acc[0], afr, bfr[0], bfr[1]);
            mma16816(acc[1], afr, bfr[2], bfr[3]);
        }
    }
}

// ---------------- fused encoder step: fp16 gates GEMM (64x32xK512) + LSTM ----------------
// grid 64: block owns interleaved n-cols [bid*32, +32) = j-dims [bid*8, +8)
__global__ void __launch_bounds__(256, 1) enc_step16(int t) {
    extern __shared__ char sm[];
    const uint32_t Ab = smem_u32(sm);
    const uint32_t Bb = Ab + 65536;
    float* gsm = (float*)(sm + 65536 + 32768);   // [64][33]
    const int tid = threadIdx.x, bid = blockIdx.x;
    const int wid = tid >> 5, lane = tid & 31;
    const int wm = wid >> 1, wn = wid & 1;

    load_AB16<8>(Ab, Bb, g_eh16[t & 1], HDIM * 2, g_We16, HDIM * 2, bid * 32, tid);

    float acc[2][4] = {{0.f, 0.f, 0.f, 0.f}, {0.f, 0.f, 0.f, 0.f}};
    mma_64x32<8>(Ab, Bb, lane, wm, wn, acc);

    const int quad = lane >> 2, tq = lane & 3;
#pragma unroll
    for (int nt = 0; nt < 2; nt++) {
        int cb = wn * 16 + nt * 8 + tq * 2;
        int r0 = wm * 16 + quad;
        gsm[r0 * 33 + cb] = acc[nt][0];
        gsm[r0 * 33 + cb + 1] = acc[nt][1];
        gsm[(r0 + 8) * 33 + cb] = acc[nt][2];
        gsm[(r0 + 8) * 33 + cb + 1] = acc[nt][3];
    }
    __syncthreads();

    const int b = tid & 63, jl = tid >> 6;
    size_t xb = ((size_t)t * 64 + b) * GDIM;
#pragma unroll
    for (int q = 0; q < 2; q++) {
        int j2 = jl + q * 4;
        int jd = bid * 8 + j2;
        float gi = gsm[b * 33 + j2 * 4 + 0] + g_xprojE[xb + jd];
        float gf = gsm[b * 33 + j2 * 4 + 1] + g_xprojE[xb + 512 + jd];
        float gg = gsm[b * 33 + j2 * 4 + 2] + g_xprojE[xb + 1024 + jd];
        float go = gsm[b * 33 + j2 * 4 + 3] + g_xprojE[xb + 1536 + jd];
        int ci = b * 512 + jd;
        float cc = sigf(gf) * g_c[ci] + sigf(gi) * tanhf(gg);
        float hh = sigf(go) * tanhf(cc);
        g_c[ci] = cc;
        g_eh16[(t + 1) & 1][ci] = __float2half(hh);
        g_encout[((size_t)b * SLEN + t) * 512 + jd] = hh;
    }
}

// ---------------- decoder hWh: fp16 GEMM (64x32xK512), direct fp32 store ----------------
// grid 16; A = xcat h-part (pitch 1024 halves), B = g_Wh16
__global__ void __launch_bounds__(256, 1) dec_hwh16(int t) {
    extern __shared__ char sm[];
    const uint32_t Ab = smem_u32(sm);
    const uint32_t Bb = Ab + 65536;
    const int tid = threadIdx.x, bid = blockIdx.x;
    const int wid = tid >> 5, lane = tid & 31;
    const int wm = wid >> 1, wn = wid & 1;

    load_AB16<8>(Ab, Bb, g_xh16[t & 1], 1024 * 2, g_Wh16, HDIM * 2, bid * 32, tid);

    float acc[2][4] = {{0.f, 0.f, 0.f, 0.f}, {0.f, 0.f, 0.f, 0.f}};
    mma_64x32<8>(Ab, Bb, lane, wm, wn, acc);

    const int quad = lane >> 2, tq = lane & 3;
#pragma unroll
    for (int nt = 0; nt < 2; nt++) {
        int n = bid * 32 + wn * 16 + nt * 8 + tq * 2;
        int r0 = wm * 16 + quad;
        g_hwh[r0 * 512 + n] = acc[nt][0];
        g_hwh[r0 * 512 + n + 1] = acc[nt][1];
        g_hwh[(r0 + 8) * 512 + n] = acc[nt][2];
        g_hwh[(r0 + 8) * 512 + n + 1] = acc[nt][3];
    }
}

// ---------------- decoder attention ----------------
__global__ void __launch_bounds__(256, 1) k_attn(const float* __restrict__ vw, int t) {
    __shared__ float hwhs[512];
    __shared__ float vws[512];
    __shared__ float sc[128];
    __shared__ float red[128];
    const int bb = blockIdx.x;
    const int tid = threadIdx.x;
    const int cur = t & 1;

    for (int i = tid; i < 512; i += 256) {
        hwhs[i] = g_hwh[bb * 512 + i];
        vws[i] = vw[i];
    }
    __syncthreads();
    int warp = tid >> 5, lane = tid & 31;
    for (int s = warp; s < SLEN; s += 8) {
        const float* we = &g_encWe[((size_t)bb * SLEN + s) * 512];
        float a = 0.0f;
        for (int j = lane; j < 512; j += 32)
            a += tanhf(hwhs[j] + we[j]) * vws[j];
#pragma unroll
        for (int o = 16; o > 0; o >>= 1) a += __shfl_xor_sync(0xffffffffu, a, o);
        if (lane == 0) sc[s] = a;
    }
    __syncthreads();
    if (tid < SLEN) red[tid] = sc[tid];
    __syncthreads();
    for (int o = 64; o > 0; o >>= 1) {
        if (tid < o) red[tid] = fmaxf(red[tid], red[tid + o]);
        __syncthreads();
    }
    float mx = red[0];
    __syncthreads();
    float e = 0.0f;
    if (tid < SLEN) { e = expf(sc[tid] - mx); red[tid] = e; }
    __syncthreads();
    for (int o = 64; o > 0; o >>= 1) {
        if (tid < o) red[tid] += red[tid + o];
        __syncthreads();
    }
    float inv = 1.0f / red[0];
    __syncthreads();
    if (tid < SLEN) sc[tid] = e * inv;
    __syncthreads();

    float c0 = 0.0f, c1 = 0.0f;
    const float* eo = &g_encout[(size_t)bb * SLEN * 512];
    for (int s = 0; s < SLEN; s++) {
        float w = sc[s];
        c0 += w * eo[s * 512 + tid];
        c1 += w * eo[s * 512 + tid + 256];
    }
    __half h0 = __float2half(c0), h1 = __float2half(c1);
    g_xh16[cur][bb * 1024 + 512 + tid] = h0;
    g_xh16[cur][bb * 1024 + 512 + tid + 256] = h1;
    size_t ma = ((size_t)t * 64 + bb) * 1024;
    g_Ahf[ma + 512 + tid] = h0;
    g_Ahf[ma + 512 + tid + 256] = h1;
}

// ---------------- fused decoder gates: fp16 GEMM (64x32xK1024) + LSTM ----------------
// grid 64; writes h fp16 to xcat[next] + fc A-matrix row t
__global__ void __launch_bounds__(256, 1) dec_gates16(int t) {
    extern __shared__ char sm[];
    const uint32_t Ab = smem_u32(sm);
    const uint32_t Bb = Ab + 131072;
    float* gsm = (float*)(sm + 131072 + 65536);   // [64][33]
    const int tid = threadIdx.x, bid = blockIdx.x;
    const int wid = tid >> 5, lane = tid & 31;
    const int wm = wid >> 1, wn = wid & 1;

    load_AB16<16>(Ab, Bb, g_xh16[t & 1], 1024 * 2, g_Wd16, 1024 * 2, bid * 32, tid);

    float acc[2][4] = {{0.f, 0.f, 0.f, 0.f}, {0.f, 0.f, 0.f, 0.f}};
    mma_64x32<16>(Ab, Bb, lane, wm, wn, acc);

    const int quad = lane >> 2, tq = lane & 3;
#pragma unroll
    for (int nt = 0; nt < 2; nt++) {
        int cb = wn * 16 + nt * 8 + tq * 2;
        int r0 = wm * 16 + quad;
        gsm[r0 * 33 + cb] = acc[nt][0];
        gsm[r0 * 33 + cb + 1] = acc[nt][1];
        gsm[(r0 + 8) * 33 + cb] = acc[nt][2];
        gsm[(r0 + 8) * 33 + cb + 1] = acc[nt][3];
    }
    __syncthreads();

    const int b = tid & 63, jl = tid >> 6;
    size_t xb = ((size_t)t * 64 + b) * GDIM;
#pragma unroll
    for (int q = 0; q < 2; q++) {
        int j2 = jl + q * 4;
        int jd = bid * 8 + j2;
        float gi = gsm[b * 33 + j2 * 4 + 0] + g_decxp[xb + jd];
        float gf = gsm[b * 33 + j2 * 4 + 1] + g_decxp[xb + 512 + jd];
        float gg = gsm[b * 33 + j2 * 4 + 2] + g_decxp[xb + 1024 + jd];
        float go = gsm[b * 33 + j2 * 4 + 3] + g_decxp[xb + 1536 + jd];
        int ci = b * 512 + jd;
        float cc = sigf(gf) * g_c[ci] + sigf(gi) * tanhf(gg);
        float hh = sigf(go) * tanhf(cc);
        g_c[ci] = cc;
        __half h16 = __float2half(hh);
        g_xh16[(t + 1) & 1][b * 1024 + jd] = h16;
        g_Ahf[((size_t)t * 64 + b) * 1024 + jd] = h16;
    }
}

// ---------------- fp16 tensor-core fc GEMM (mma.sync) ----------------
__global__ void __launch_bounds__(256, 1) hgemm_fc(const float* __restrict__ fc_b,
                                                   float* __restrict__ out) {
    extern __shared__ char smc[];
    const uint32_t sbase = smem_u32(smc);
    const int tid = threadIdx.x;
    const int wid = tid >> 5, lane = tid & 31;
    const int m0 = blockIdx.x * 128;
    const int n0 = blockIdx.y * 128;
    const int wm = wid >> 2;
    const int wn = wid & 3;

    const char* Ag = (const char*)g_Ahf + (size_t)m0 * (KD * 2);
    const char* Bg = (const char*)g_Bhf + (size_t)n0 * (KD * 2);

    float acc[4][4][4];
#pragma unroll
    for (int i = 0; i < 4; i++)
#pragma unroll
        for (int j = 0; j < 4; j++)
#pragma unroll
            for (int r = 0; r < 4; r++) acc[i][j][r] = 0.0f;

    auto load_chunk = [&](int kc, int slot) {
        uint32_t st = sbase + (uint32_t)slot * STGB;
#pragma unroll
        for (int i = 0; i < 8; i++) {
            int idx = tid + (i << 8);
            int isB = idx >> 10;
            int r = (idx & 1023) >> 3;
            int seg = idx & 7;
            uint32_t dst = st + (isB ? 16384u : 0u) + (uint32_t)(r << 7)
                         + (uint32_t)(((seg ^ (r & 7)) << 4));
            const char* src = (isB ? Bg : Ag) + (size_t)r * (KD * 2) + (size_t)kc * 128 + (seg << 4);
            cpa16(dst, src);
        }
        cpa_commit();
    };

    const int g = lane >> 3, lr = lane & 7;

    auto compute = [&](int slot) {
        uint32_t Abase = sbase + (uint32_t)slot * STGB;
        uint32_t Bbase = Abase + 16384u;
#pragma unroll
        for (int ks = 0; ks < 4; ks++) {
            uint32_t afr[4][4];
#pragma unroll
            for (int mt = 0; mt < 4; mt++) {
                int row = wm * 64 + mt * 16 + (g & 1) * 8 + lr;
                int kseg = ks * 2 + (g >> 1);
                uint32_t addr = Abase + (uint32_t)(row << 7) + (uint32_t)(((kseg ^ (row & 7)) << 4));
                LDMX4(afr[mt], addr);
            }
            uint32_t bfr[2][4];
#pragma unroll
            for (int np = 0; np < 2; np++) {
                int row = wn * 32 + np * 16 + (g >> 1) * 8 + lr;
                int kseg = ks * 2 + (g & 1);
                uint32_t addr = Bbase + (uint32_t)(row << 7) + (uint32_t)(((kseg ^ (row & 7)) << 4));
                LDMX4(bfr[np], addr);
            }
#pragma unroll
            for (int mt = 0; mt < 4; mt++)
#pragma unroll
                for (int nt = 0; nt < 4; nt++) {
                    const uint32_t* bp = &bfr[nt >> 1][(nt & 1) * 2];
                    mma16816(acc[mt][nt], afr[mt], bp[0], bp[1]);
                }
        }
    };

    load_chunk(0, 0);
    load_chunk(1, 1);
    for (int i = 0; i < NCHK; i++) {
        if (i + 1 < NCHK) cpa_wait<1>(); else cpa_wait<0>();
        __syncthreads();
        if (i + 2 < NCHK) load_chunk(i + 2, (i + 2) % 3);
        compute(i % 3);
    }

    const int quad = lane >> 2, tq = lane & 3;
#pragma unroll
    for (int mt = 0; mt < 4; mt++) {
        int mr0 = m0 + wm * 64 + mt * 16 + quad;
#pragma unroll
        for (int half = 0; half < 2; half++) {
            int m = mr0 + half * 8;
            if (m >= TD * BATCH) continue;
            int bb = m & 63, tt = m >> 6;
            float* orow = out + ((size_t)bb * TLEN + (tt + 1)) * VCAB;
#pragma unroll
            for (int nt = 0; nt < 4; nt++) {
                int n = n0 + wn * 32 + nt * 8 + tq * 2;
                float v0 = acc[mt][nt][half * 2 + 0];
                float v1 = acc[mt][nt][half * 2 + 1];
                if (n < VCAB)     orow[n]     = v0 + fc_b[n];
                if (n + 1 < VCAB) orow[n + 1] = v1 + fc_b[n + 1];
            }
        }
    }
}

// ---------------- generic tiled SGEMM: C[M,N] = A[M,K] @ B[N,K]^T + bias ----------------
__global__ void sgemm64(int M, int N, int K,
                        int asel, int lda,
                        const float* __restrict__ Bp, int ldb,
                        int csel, int ldc,
                        int bsel, const float* __restrict__ biasp) {
    const float* A = (asel == 0) ? g_encX : (asel == 1) ? g_decX : g_encout;
    float* C = (csel == 0) ? g_xprojE : (csel == 1) ? g_decxp : g_encWe;
    const float* bias = (bsel == 0) ? g_benc : (bsel == 1) ? g_bdec : biasp;

    __shared__ __align__(16) float As[16][64];
    __shared__ __align__(16) float Bs[16][64];

    const int tid = threadIdx.x;
    const int tx = tid & 15, ty = tid >> 4;
    const int m0 = blockIdx.y * 64, n0 = blockIdx.x * 64;
    const int lr = tid >> 2;
    const int lk = (tid & 3) << 2;

    float acc[4][4];
#pragma unroll
    for (int i = 0; i < 4; i++)
#pragma unroll
        for (int j = 0; j < 4; j++) acc[i][j] = 0.0f;

    const bool brow_ok = (n0 + lr) < N;
    const float* Arow = A + (size_t)(m0 + lr) * lda;
    const float* Brow = Bp + (size_t)(n0 + lr) * ldb;

    for (int k0 = 0; k0 < K; k0 += 16) {
        float4 av = *reinterpret_cast<const float4*>(Arow + k0 + lk);
        float4 bv = make_float4(0.f, 0.f, 0.f, 0.f);
        if (brow_ok) bv = *reinterpret_cast<const float4*>(Brow + k0 + lk);
        As[lk + 0][lr] = av.x; As[lk + 1][lr] = av.y; As[lk + 2][lr] = av.z; As[lk + 3][lr] = av.w;
        Bs[lk + 0][lr] = bv.x; Bs[lk + 1][lr] = bv.y; Bs[lk + 2][lr] = bv.z; Bs[lk + 3][lr] = bv.w;
        __syncthreads();
#pragma unroll
        for (int kk = 0; kk < 16; kk++) {
            float4 a = *reinterpret_cast<const float4*>(&As[kk][ty << 2]);
            float4 b = *reinterpret_cast<const float4*>(&Bs[kk][tx << 2]);
            float ar[4] = {a.x, a.y, a.z, a.w};
            float br[4] = {b.x, b.y, b.z, b.w};
#pragma unroll
            for (int i = 0; i < 4; i++)
#pragma unroll
                for (int j = 0; j < 4; j++) acc[i][j] += ar[i] * br[j];
        }
        __syncthreads();
    }

#pragma unroll
    for (int i = 0; i < 4; i++) {
        int m = m0 + (ty << 2) + i;
#pragma unroll
        for (int j = 0; j < 4; j++) {
            int n = n0 + (tx << 2) + j;
            if (n < N) C[(size_t)m * ldc + n] = acc[i][j] + bias[n];
        }
    }
}

// ---------------- host driver ----------------
extern "C" void kernel_launch(void* const* d_in, const int* in_sizes, int n_in,
                              void* d_out, int out_size) {
    const int*   src     = (const int*)  d_in[0];
    const int*   trg     = (const int*)  d_in[1];
    const float* enc_emb = (const float*)d_in[2];
    const float* enc_Wih = (const float*)d_in[3];
    const float* enc_Whh = (const float*)d_in[4];
    const float* enc_bih = (const float*)d_in[5];
    const float* enc_bhh = (const float*)d_in[6];
    const float* dec_emb = (const float*)d_in[7];
    const float* dec_Wih = (const float*)d_in[8];
    const float* dec_Whh = (const float*)d_in[9];
    const float* dec_bih = (const float*)d_in[10];
    const float* dec_bhh = (const float*)d_in[11];
    const float* attn_W  = (const float*)d_in[12];
    const float* attn_b  = (const float*)d_in[13];
    const float* v_w     = (const float*)d_in[14];
    const float* fc_W    = (const float*)d_in[15];
    const float* fc_b    = (const float*)d_in[16];
    float* out = (float*)d_out;
    (void)in_sizes; (void)n_in; (void)out_size;

    const int ENC_SMEM = 65536 + 32768 + 64 * 33 * 4;        // 106752
    const int HWH_SMEM = 65536 + 32768;                      // 98304
    const int DEC_SMEM = 131072 + 65536 + 64 * 33 * 4;       // 205056
    cudaFuncSetAttribute(hgemm_fc, cudaFuncAttributeMaxDynamicSharedMemorySize, 3 * STGB);
    cudaFuncSetAttribute(enc_step16, cudaFuncAttributeMaxDynamicSharedMemorySize, ENC_SMEM);
    cudaFuncSetAttribute(dec_hwh16, cudaFuncAttributeMaxDynamicSharedMemorySize, HWH_SMEM);
    cudaFuncSetAttribute(dec_gates16, cudaFuncAttributeMaxDynamicSharedMemorySize, DEC_SMEM);

    // setup
    k_bias<<<8, 256>>>(enc_bih, enc_bhh, dec_bih, dec_bhh);
    k_w16_enc<<<(int)(((size_t)GDIM * HDIM + 255) / 256), 256>>>(enc_Whh);
    k_w16_dec<<<(int)(((size_t)GDIM * 1024 + 255) / 256), 256>>>(dec_Wih, dec_Whh);
    k_w16_wh<<<(int)(((size_t)HDIM * HDIM + 255) / 256), 256>>>(attn_W);
    k_gather_enc<<<SLEN * BATCH, EDIM>>>(enc_emb, src);
    k_gather_dec<<<TD * BATCH, EDIM>>>(dec_emb, trg);
    k_zero_out<<<(int)(((size_t)BATCH * VCAB + 255) / 256), 256>>>(out);
    k_zero_state<<<(BATCH * HDIM + 255) / 256, 256>>>();
    k_convB_h<<<(int)(((size_t)VCAB * KD / 4 + 255) / 256), 256>>>(fc_W);

    // batched input projections (fp32, include biases)
    sgemm64<<<dim3(GDIM / 64, (SLEN * BATCH) / 64), 256>>>(
        SLEN * BATCH, GDIM, EDIM, 0, EDIM, enc_Wih, EDIM, 0, GDIM, 0, nullptr);
    sgemm64<<<dim3(GDIM / 64, (TD * BATCH) / 64), 256>>>(
        TD * BATCH, GDIM, EDIM, 1, EDIM, dec_Wih, EDIM + HDIM, 1, GDIM, 1, nullptr);

    // encoder: ONE fused fp16-mma kernel per step
    for (int t = 0; t < SLEN; t++)
        enc_step16<<<64, 256, ENC_SMEM>>>(t);

    // encWe = enc_out @ attn_W[:, H:]^T + attn_b (fp32)
    sgemm64<<<dim3(HDIM / 64, (BATCH * SLEN) / 64), 256>>>(
        BATCH * SLEN, HDIM, HDIM, 2, HDIM, attn_W + HDIM, 2 * HDIM, 2, HDIM, 2, attn_b);

    k_init_dec<<<128, 256>>>();

    // decoder: THREE kernels per step (hwh fp16-mma, attention, fused gates+LSTM fp16-mma)
    for (int t = 0; t < TD; t++) {
        dec_hwh16<<<16, 256, HWH_SMEM>>>(t);
        k_attn<<<64, 256>>>(v_w, t);
        dec_gates16<<<64, 256, DEC_SMEM>>>(t);
    }

    // tensor-core fc GEMM
    hgemm_fc<<<dim3(MPAD / 128, NPAD / 128), 256, 3 * STGB>>>(fc_b, out);
}

// round 10
// speedup vs baseline: 1.9577x; 1.1719x over previous
#include <cuda_runtime.h>
#include <cuda_fp16.h>
#include <math.h>
#include <stdint.h>

#define VCAB 50257
#define EDIM 256
#define HDIM 512
#define BATCH 64
#define SLEN 128
#define TLEN 64
#define TD 63            // decoder steps (T-1)
#define GDIM 2048        // 4*H

// fc GEMM dims (fp16 mma.sync path)
#define KD 1024
#define MPAD 4096
#define NPAD 50432       // 197 * 256
#define NCHK 16          // KD / 64
#define STGB 49152       // fc stage bytes: A 16KB + B 32KB

// ---------------- scratch (static device allocations; no cudaMalloc) ----------------
__device__ __align__(16) float g_bIenc[GDIM];                       // interleaved bias
__device__ __align__(16) float g_bIdec[GDIM];
__device__ __align__(16) float g_xprojE[(size_t)SLEN * BATCH * GDIM];  // INTERLEAVED [m][j*4+g]
__device__ __align__(16) float g_decxp[(size_t)MPAD * GDIM];           // INTERLEAVED
__device__ __align__(16) float g_encout[(size_t)BATCH * SLEN * HDIM];
__device__ __align__(16) float g_encWe[(size_t)BATCH * SLEN * HDIM];
__device__ __align__(16) float g_c[BATCH * HDIM];
__device__ __align__(16) float g_hwh[BATCH * HDIM];
// fp16 embeddings (proj GEMM A operands; pad rows of decX16 stay zero)
__device__ __align__(16) __half g_encX16[(size_t)SLEN * BATCH * EDIM];
__device__ __align__(16) __half g_decX16[(size_t)MPAD * EDIM];
// fp16 recurrent state
__device__ __align__(16) __half g_eh16[2][BATCH * HDIM];
__device__ __align__(16) __half g_xh16[2][BATCH * 1024];
// fp16 gate-interleaved weights: row n = j*4 + gate (i,f,g,o), cols = k
__device__ __align__(16) __half g_We16[(size_t)GDIM * HDIM];        // enc Whh    [2048][512]
__device__ __align__(16) __half g_Wd16[(size_t)GDIM * 1024];        // dec packed [2048][1024]
__device__ __align__(16) __half g_Wh16[(size_t)HDIM * HDIM];        // attn Wh    [512][512]
__device__ __align__(16) __half g_WihE16[(size_t)GDIM * EDIM];      // enc Wih    [2048][256]
__device__ __align__(16) __half g_WihD16[(size_t)GDIM * EDIM];      // dec Wih emb part
// fp16 operands for the tensor-core fc GEMM (pad rows stay zero: never written)
__device__ __align__(16) __half g_Ahf[(size_t)MPAD * KD];
__device__ __align__(16) __half g_Bhf[(size_t)NPAD * KD];

__device__ __forceinline__ float sigf(float x) { return 1.0f / (1.0f + expf(-x)); }

// ---------------- PTX helpers (compute_103-safe) ----------------
__device__ __forceinline__ uint32_t smem_u32(const void* p) {
    uint32_t a;
    asm("{ .reg .u64 t; cvta.to.shared.u64 t, %1; cvt.u32.u64 %0, t; }" : "=r"(a) : "l"(p));
    return a;
}
__device__ __forceinline__ void cpa16(uint32_t dst, const void* src) {
    asm volatile("cp.async.cg.shared.global [%0], [%1], 16;" :: "r"(dst), "l"(src) : "memory");
}
__device__ __forceinline__ void cpa_commit() { asm volatile("cp.async.commit_group;" ::: "memory"); }
template <int N> __device__ __forceinline__ void cpa_wait() {
    asm volatile("cp.async.wait_group %0;" :: "n"(N) : "memory");
}
#define LDMX4(r, addr) \
    asm volatile("ldmatrix.sync.aligned.m8n8.x4.shared.b16 {%0,%1,%2,%3}, [%4];" \
        : "=r"((r)[0]), "=r"((r)[1]), "=r"((r)[2]), "=r"((r)[3]) : "r"(addr))
__device__ __forceinline__ void mma16816(float* c, const uint32_t* a, uint32_t b0, uint32_t b1) {
    asm volatile("mma.sync.aligned.m16n8k16.row.col.f32.f16.f16.f32 "
        "{%0,%1,%2,%3}, {%4,%5,%6,%7}, {%8,%9}, {%0,%1,%2,%3};"
        : "+f"(c[0]), "+f"(c[1]), "+f"(c[2]), "+f"(c[3])
        : "r"(a[0]), "r"(a[1]), "r"(a[2]), "r"(a[3]), "r"(b0), "r"(b1));
}

// ---------------- setup kernels ----------------
__global__ void k_biasI(const float* __restrict__ ebih, const float* __restrict__ ebhh,
                        const float* __restrict__ dbih, const float* __restrict__ dbhh) {
    int n = blockIdx.x * blockDim.x + threadIdx.x;
    if (n < GDIM) {
        int j = n >> 2, g = n & 3;
        int r = g * 512 + j;
        g_bIenc[n] = ebih[r] + ebhh[r];
        g_bIdec[n] = dbih[r] + dbhh[r];
    }
}

__global__ void k_w16_enc(const float* __restrict__ Whh) {
    size_t idx = (size_t)blockIdx.x * blockDim.x + threadIdx.x;
    if (idx >= (size_t)GDIM * HDIM) return;
    int n = (int)(idx >> 9);
    int k = (int)(idx & 511);
    int j = n >> 2, g = n & 3;
    g_We16[idx] = __float2half(Whh[(size_t)(g * 512 + j) * 512 + k]);
}

__global__ void k_w16_dec(const float* __restrict__ dWih, const float* __restrict__ dWhh) {
    size_t idx = (size_t)blockIdx.x * blockDim.x + threadIdx.x;
    if (idx >= (size_t)GDIM * 1024) return;
    int n = (int)(idx >> 10);
    int k = (int)(idx & 1023);
    int j = n >> 2, g = n & 3;
    int row = g * 512 + j;
    float v = (k < 512) ? dWhh[(size_t)row * 512 + k]
                        : dWih[(size_t)row * (EDIM + HDIM) + EDIM + (k - 512)];
    g_Wd16[idx] = __float2half(v);
}

__global__ void k_w16_wh(const float* __restrict__ attnW) {
    size_t idx = (size_t)blockIdx.x * blockDim.x + threadIdx.x;
    if (idx >= (size_t)HDIM * HDIM) return;
    int n = (int)(idx >> 9);
    int k = (int)(idx & 511);
    g_Wh16[idx] = __float2half(attnW[(size_t)n * 1024 + k]);
}

// enc/dec Wih (embedding part) -> fp16 gate-interleaved [n=j*4+g][k 0..255]
__global__ void k_w16_wih(const float* __restrict__ eWih, const float* __restrict__ dWih) {
    size_t idx = (size_t)blockIdx.x * blockDim.x + threadIdx.x;
    if (idx >= (size_t)GDIM * EDIM) return;
    int n = (int)(idx >> 8);
    int k = (int)(idx & 255);
    int j = n >> 2, g = n & 3;
    int row = g * 512 + j;
    g_WihE16[idx] = __float2half(eWih[(size_t)row * EDIM + k]);
    g_WihD16[idx] = __float2half(dWih[(size_t)row * (EDIM + HDIM) + k]);
}

__global__ void k_gather_enc(const float* __restrict__ emb, const int* __restrict__ src) {
    int m = blockIdx.x;
    int e = threadIdx.x;
    int s = m >> 6, b = m & 63;
    int tok = src[b * SLEN + s];
    g_encX16[(size_t)m * EDIM + e] = __float2half(emb[(size_t)tok * EDIM + e]);
}

__global__ void k_gather_dec(const float* __restrict__ emb, const int* __restrict__ trg) {
    int m = blockIdx.x;
    int e = threadIdx.x;
    int t = m >> 6, b = m & 63;
    int tok = trg[b * TLEN + t];
    g_decX16[(size_t)m * EDIM + e] = __float2half(emb[(size_t)tok * EDIM + e]);
}

__global__ void k_zero_out(float* __restrict__ out) {
    size_t idx = (size_t)blockIdx.x * blockDim.x + threadIdx.x;
    if (idx >= (size_t)BATCH * VCAB) return;
    size_t b = idx / VCAB, v = idx % VCAB;
    out[b * (size_t)TLEN * VCAB + v] = 0.0f;
}

__global__ void k_zero_state() {
    int i = blockIdx.x * blockDim.x + threadIdx.x;
    if (i < BATCH * HDIM) {
        g_eh16[0][i] = __float2half(0.0f);
        g_c[i] = 0.0f;
    }
}

__global__ void k_init_dec() {
    int i = blockIdx.x * blockDim.x + threadIdx.x;
    int b = i >> 9, j = i & 511;
    g_xh16[0][b * 1024 + j] = g_eh16[0][b * 512 + j];
}

__global__ void k_convB_h(const float* __restrict__ W) {
    size_t i4 = (size_t)blockIdx.x * blockDim.x + threadIdx.x;
    if (i4 * 4 >= (size_t)VCAB * KD) return;
    float4 v = *reinterpret_cast<const float4*>(W + i4 * 4);
    __half2* dst = reinterpret_cast<__half2*>(g_Bhf + i4 * 4);
    dst[0] = __floats2half2_rn(v.x, v.y);
    dst[1] = __floats2half2_rn(v.z, v.w);
}

// ============ shared fp16 GEMM tile machinery ============
template <int NCH>
__device__ __forceinline__ void load_AB16(uint32_t Ab, uint32_t Bb,
                                          const __half* __restrict__ Aglob, int apitchB,
                                          const __half* __restrict__ Bglob, int bpitchB,
                                          int n0, int tid) {
    for (int i = tid; i < 64 * 8 * NCH; i += 256) {
        int kc = i >> 9, rem = i & 511;
        int r = rem >> 3, s = rem & 7;
        uint32_t dst = Ab + kc * 8192 + (r << 7) + (((s ^ (r & 7)) << 4));
        const char* src = (const char*)Aglob + (size_t)r * apitchB + kc * 128 + (s << 4);
        cpa16(dst, src);
    }
    for (int i = tid; i < 32 * 8 * NCH; i += 256) {
        int kc = i >> 8, rem = i & 255;
        int r = rem >> 3, s = rem & 7;
        uint32_t dst = Bb + kc * 4096 + (r << 7) + (((s ^ (r & 7)) << 4));
        const char* src = (const char*)Bglob + (size_t)(n0 + r) * bpitchB + kc * 128 + (s << 4);
        cpa16(dst, src);
    }
    cpa_commit();
    cpa_wait<0>();
    __syncthreads();
}

template <int NCH>
__device__ __forceinline__ void mma_64x32(uint32_t Ab, uint32_t Bb, int lane, int wm, int wn,
                                          float acc[2][4]) {
    const int g = lane >> 3, lr = lane & 7;
    for (int kc = 0; kc < NCH; kc++) {
#pragma unroll
        for (int ks = 0; ks < 4; ks++) {
            uint32_t afr[4], bfr[4];
            {
                int row = wm * 16 + (g & 1) * 8 + lr;
                int kseg = ks * 2 + (g >> 1);
                uint32_t addr = Ab + kc * 8192 + (row << 7) + (((kseg ^ (row & 7)) << 4));
                LDMX4(afr, addr);
            }
            {
                int row = wn * 16 + (g >> 1) * 8 + lr;
                int kseg = ks * 2 + (g & 1);
                uint32_t addr = Bb + kc * 4096 + (row << 7) + (((kseg ^ (row & 7)) << 4));
                LDMX4(bfr, addr);
            }
            mma16816(acc[0], afr, bfr[0], bfr[1]);
            mma16816(acc[1], afr, bfr[2], bfr[3]);
        }
    }
}

// ---------------- fp16 input-projection GEMM: C[m][2048] interleaved, K=256 ----------------
// sel 0: encoder (A=g_encX16, B=g_WihE16, bias=g_bIenc, C=g_xprojE, Mlim=8192)
// sel 1: decoder (A=g_decX16, B=g_WihD16, bias=g_bIdec, C=g_decxp, Mlim=4032)
// tile 128x128, 8 warps 2(M)x4(N)
__global__ void __launch_bounds__(256, 1) hgemm_proj(int sel) {
    const __half* A = sel ? g_decX16 : g_encX16;
    const __half* B = sel ? g_WihD16 : g_WihE16;
    const float* biasI = sel ? g_bIdec : g_bIenc;
    float* C = sel ? g_decxp : g_xprojE;
    const int Mlim = sel ? (TD * BATCH) : (SLEN * BATCH);

    constexpr int NC = 4;               // 256 / 64
    extern __shared__ char smc[];
    const uint32_t sbase = smem_u32(smc);
    const int tid = threadIdx.x;
    const int wid = tid >> 5, lane = tid & 31;
    const int m0 = blockIdx.x * 128;
    const int n0 = blockIdx.y * 128;
    const int wm = wid >> 2, wn = wid & 3;

    const char* Ag = (const char*)A + (size_t)m0 * (EDIM * 2);
    const char* Bg = (const char*)B + (size_t)n0 * (EDIM * 2);

    float acc[4][4][4];
#pragma unroll
    for (int i = 0; i < 4; i++)
#pragma unroll
        for (int j = 0; j < 4; j++)
#pragma unroll
            for (int r = 0; r < 4; r++) acc[i][j][r] = 0.0f;

    auto load_chunk = [&](int kc, int slot) {
        uint32_t st = sbase + (uint32_t)slot * 32768;
#pragma unroll
        for (int i = 0; i < 8; i++) {
            int idx = tid + (i << 8);
            int isB = idx >> 10;
            int r = (idx & 1023) >> 3;
            int seg = idx & 7;
            uint32_t dst = st + (isB ? 16384u : 0u) + (uint32_t)(r << 7)
                         + (uint32_t)(((seg ^ (r & 7)) << 4));
            const char* src = (isB ? Bg : Ag) + (size_t)r * (EDIM * 2) + (size_t)kc * 128 + (seg << 4);
            cpa16(dst, src);
        }
        cpa_commit();
    };

    const int g = lane >> 3, lr = lane & 7;
    auto compute = [&](int slot) {
        uint32_t Abase = sbase + (uint32_t)slot * 32768;
        uint32_t Bbase = Abase + 16384u;
#pragma unroll
        for (int ks = 0; ks < 4; ks++) {
            uint32_t afr[4][4];
#pragma unroll
            for (int mt = 0; mt < 4; mt++) {
                int row = wm * 64 + mt * 16 + (g & 1) * 8 + lr;
                int kseg = ks * 2 + (g >> 1);
                uint32_t addr = Abase + (uint32_t)(row << 7) + (uint32_t)(((kseg ^ (row & 7)) << 4));
                LDMX4(afr[mt], addr);
            }
            uint32_t bfr[2][4];
#pragma unroll
            for (int np = 0; np < 2; np++) {
                int row = wn * 32 + np * 16 + (g >> 1) * 8 + lr;
                int kseg = ks * 2 + (g & 1);
                uint32_t addr = Bbase + (uint32_t)(row << 7) + (uint32_t)(((kseg ^ (row & 7)) << 4));
                LDMX4(bfr[np], addr);
            }
#pragma unroll
            for (int mt = 0; mt < 4; mt++)
#pragma unroll
                for (int nt = 0; nt < 4; nt++) {
                    const uint32_t* bp = &bfr[nt >> 1][(nt & 1) * 2];
                    mma16816(acc[mt][nt], afr[mt], bp[0], bp[1]);
                }
        }
    };

    load_chunk(0, 0);
    load_chunk(1, 1);
    for (int i = 0; i < NC; i++) {
        if (i + 1 < NC) cpa_wait<1>(); else cpa_wait<0>();
        __syncthreads();
        if (i + 2 < NC) load_chunk(i + 2, (i + 2) % 3);
        compute(i % 3);
    }

    const int quad = lane >> 2, tq = lane & 3;
#pragma unroll
    for (int mt = 0; mt < 4; mt++) {
        int mr0 = m0 + wm * 64 + mt * 16 + quad;
#pragma unroll
        for (int half = 0; half < 2; half++) {
            int m = mr0 + half * 8;
            if (m >= Mlim) continue;
            float* crow = C + (size_t)m * GDIM;
#pragma unroll
            for (int nt = 0; nt < 4; nt++) {
                int n = n0 + wn * 32 + nt * 8 + tq * 2;
                crow[n] = acc[mt][nt][half * 2 + 0] + biasI[n];
                crow[n + 1] = acc[mt][nt][half * 2 + 1] + biasI[n + 1];
            }
        }
    }
}

// ---------------- fused encoder step: fp16 gates GEMM (64x32xK512) + LSTM ----------------
__global__ void __launch_bounds__(256, 1) enc_step16(int t) {
    extern __shared__ char sm[];
    const uint32_t Ab = smem_u32(sm);
    const uint32_t Bb = Ab + 65536;
    float* gsm = (float*)(sm + 65536 + 32768);   // [64][33]
    const int tid = threadIdx.x, bid = blockIdx.x;
    const int wid = tid >> 5, lane = tid & 31;
    const int wm = wid >> 1, wn = wid & 1;

    load_AB16<8>(Ab, Bb, g_eh16[t & 1], HDIM * 2, g_We16, HDIM * 2, bid * 32, tid);

    float acc[2][4] = {{0.f, 0.f, 0.f, 0.f}, {0.f, 0.f, 0.f, 0.f}};
    mma_64x32<8>(Ab, Bb, lane, wm, wn, acc);

    const int quad = lane >> 2, tq = lane & 3;
#pragma unroll
    for (int nt = 0; nt < 2; nt++) {
        int cb = wn * 16 + nt * 8 + tq * 2;
        int r0 = wm * 16 + quad;
        gsm[r0 * 33 + cb] = acc[nt][0];
        gsm[r0 * 33 + cb + 1] = acc[nt][1];
        gsm[(r0 + 8) * 33 + cb] = acc[nt][2];
        gsm[(r0 + 8) * 33 + cb + 1] = acc[nt][3];
    }
    __syncthreads();

    const int b = tid & 63, jl = tid >> 6;
#pragma unroll
    for (int q = 0; q < 2; q++) {
        int j2 = jl + q * 4;
        int jd = bid * 8 + j2;
        float4 gv = *reinterpret_cast<const float4*>(
            &g_xprojE[((size_t)t * 64 + b) * GDIM + (size_t)jd * 4]);
        float gi = gsm[b * 33 + j2 * 4 + 0] + gv.x;
        float gf = gsm[b * 33 + j2 * 4 + 1] + gv.y;
        float gg = gsm[b * 33 + j2 * 4 + 2] + gv.z;
        float go = gsm[b * 33 + j2 * 4 + 3] + gv.w;
        int ci = b * 512 + jd;
        float cc = sigf(gf) * g_c[ci] + sigf(gi) * tanhf(gg);
        float hh = sigf(go) * tanhf(cc);
        g_c[ci] = cc;
        g_eh16[(t + 1) & 1][ci] = __float2half(hh);
        g_encout[((size_t)b * SLEN + t) * 512 + jd] = hh;
    }
}

// ---------------- decoder hWh: fp16 GEMM (64x32xK512), direct fp32 store ----------------
__global__ void __launch_bounds__(256, 1) dec_hwh16(int t) {
    extern __shared__ char sm[];
    const uint32_t Ab = smem_u32(sm);
    const uint32_t Bb = Ab + 65536;
    const int tid = threadIdx.x, bid = blockIdx.x;
    const int wid = tid >> 5, lane = tid & 31;
    const int wm = wid >> 1, wn = wid & 1;

    load_AB16<8>(Ab, Bb, g_xh16[t & 1], 1024 * 2, g_Wh16, HDIM * 2, bid * 32, tid);

    float acc[2][4] = {{0.f, 0.f, 0.f, 0.f}, {0.f, 0.f, 0.f, 0.f}};
    mma_64x32<8>(Ab, Bb, lane, wm, wn, acc);

    const int quad = lane >> 2, tq = lane & 3;
#pragma unroll
    for (int nt = 0; nt < 2; nt++) {
        int n = bid * 32 + wn * 16 + nt * 8 + tq * 2;
        int r0 = wm * 16 + quad;
        g_hwh[r0 * 512 + n] = acc[nt][0];
        g_hwh[r0 * 512 + n + 1] = acc[nt][1];
        g_hwh[(r0 + 8) * 512 + n] = acc[nt][2];
        g_hwh[(r0 + 8) * 512 + n + 1] = acc[nt][3];
    }
}

// ---------------- decoder attention ----------------
__global__ void __launch_bounds__(256, 1) k_attn(const float* __restrict__ vw, int t) {
    __shared__ float hwhs[512];
    __shared__ float vws[512];
    __shared__ float sc[128];
    __shared__ float red[128];
    const int bb = blockIdx.x;
    const int tid = threadIdx.x;
    const int cur = t & 1;

    for (int i = tid; i < 512; i += 256) {
        hwhs[i] = g_hwh[bb * 512 + i];
        vws[i] = vw[i];
    }
    __syncthreads();
    int warp = tid >> 5, lane = tid & 31;
    for (int s = warp; s < SLEN; s += 8) {
        const float* we = &g_encWe[((size_t)bb * SLEN + s) * 512];
        float a = 0.0f;
        for (int j = lane; j < 512; j += 32)
            a += tanhf(hwhs[j] + we[j]) * vws[j];
#pragma unroll
        for (int o = 16; o > 0; o >>= 1) a += __shfl_xor_sync(0xffffffffu, a, o);
        if (lane == 0) sc[s] = a;
    }
    __syncthreads();
    if (tid < SLEN) red[tid] = sc[tid];
    __syncthreads();
    for (int o = 64; o > 0; o >>= 1) {
        if (tid < o) red[tid] = fmaxf(red[tid], red[tid + o]);
        __syncthreads();
    }
    float mx = red[0];
    __syncthreads();
    float e = 0.0f;
    if (tid < SLEN) { e = expf(sc[tid] - mx); red[tid] = e; }
    __syncthreads();
    for (int o = 64; o > 0; o >>= 1) {
        if (tid < o) red[tid] += red[tid + o];
        __syncthreads();
    }
    float inv = 1.0f / red[0];
    __syncthreads();
    if (tid < SLEN) sc[tid] = e * inv;
    __syncthreads();

    float c0 = 0.0f, c1 = 0.0f;
    const float* eo = &g_encout[(size_t)bb * SLEN * 512];
    for (int s = 0; s < SLEN; s++) {
        float w = sc[s];
        c0 += w * eo[s * 512 + tid];
        c1 += w * eo[s * 512 + tid + 256];
    }
    __half h0 = __float2half(c0), h1 = __float2half(c1);
    g_xh16[cur][bb * 1024 + 512 + tid] = h0;
    g_xh16[cur][bb * 1024 + 512 + tid + 256] = h1;
    size_t ma = ((size_t)t * 64 + bb) * 1024;
    g_Ahf[ma + 512 + tid] = h0;
    g_Ahf[ma + 512 + tid + 256] = h1;
}

// ---------------- fused decoder gates: fp16 GEMM (64x32xK1024) + LSTM ----------------
__global__ void __launch_bounds__(256, 1) dec_gates16(int t) {
    extern __shared__ char sm[];
    const uint32_t Ab = smem_u32(sm);
    const uint32_t Bb = Ab + 131072;
    float* gsm = (float*)(sm + 131072 + 65536);   // [64][33]
    const int tid = threadIdx.x, bid = blockIdx.x;
    const int wid = tid >> 5, lane = tid & 31;
    const int wm = wid >> 1, wn = wid & 1;

    load_AB16<16>(Ab, Bb, g_xh16[t & 1], 1024 * 2, g_Wd16, 1024 * 2, bid * 32, tid);

    float acc[2][4] = {{0.f, 0.f, 0.f, 0.f}, {0.f, 0.f, 0.f, 0.f}};
    mma_64x32<16>(Ab, Bb, lane, wm, wn, acc);

    const int quad = lane >> 2, tq = lane & 3;
#pragma unroll
    for (int nt = 0; nt < 2; nt++) {
        int cb = wn * 16 + nt * 8 + tq * 2;
        int r0 = wm * 16 + quad;
        gsm[r0 * 33 + cb] = acc[nt][0];
        gsm[r0 * 33 + cb + 1] = acc[nt][1];
        gsm[(r0 + 8) * 33 + cb] = acc[nt][2];
        gsm[(r0 + 8) * 33 + cb + 1] = acc[nt][3];
    }
    __syncthreads();

    const int b = tid & 63, jl = tid >> 6;
#pragma unroll
    for (int q = 0; q < 2; q++) {
        int j2 = jl + q * 4;
        int jd = bid * 8 + j2;
        float4 gv = *reinterpret_cast<const float4*>(
            &g_decxp[((size_t)t * 64 + b) * GDIM + (size_t)jd * 4]);
        float gi = gsm[b * 33 + j2 * 4 + 0] + gv.x;
        float gf = gsm[b * 33 + j2 * 4 + 1] + gv.y;
        float gg = gsm[b * 33 + j2 * 4 + 2] + gv.z;
        float go = gsm[b * 33 + j2 * 4 + 3] + gv.w;
        int ci = b * 512 + jd;
        float cc = sigf(gf) * g_c[ci] + sigf(gi) * tanhf(gg);
        float hh = sigf(go) * tanhf(cc);
        g_c[ci] = cc;
        __half h16 = __float2half(hh);
        g_xh16[(t + 1) & 1][b * 1024 + jd] = h16;
        g_Ahf[((size_t)t * 64 + b) * 1024 + jd] = h16;
    }
}

// ---------------- fp16 tensor-core fc GEMM: tile 128M x 256N, K=1024 ----------------
__global__ void __launch_bounds__(256, 1) hgemm_fc(const float* __restrict__ fc_b,
                                                   float* __restrict__ out) {
    extern __shared__ char smc[];
    const uint32_t sbase = smem_u32(smc);
    const int tid = threadIdx.x;
    const int wid = tid >> 5, lane = tid & 31;
    const int m0 = blockIdx.x * 128;
    const int n0 = blockIdx.y * 256;
    const int wm = wid >> 2;        // 0..1 (64 M rows)
    const int wn = wid & 3;         // 0..3 (64 N cols)

    const char* Ag = (const char*)g_Ahf + (size_t)m0 * (KD * 2);
    const char* Bg = (const char*)g_Bhf + (size_t)n0 * (KD * 2);

    float acc[4][8][4];
#pragma unroll
    for (int i = 0; i < 4; i++)
#pragma unroll
        for (int j = 0; j < 8; j++)
#pragma unroll
            for (int r = 0; r < 4; r++) acc[i][j][r] = 0.0f;

    auto load_chunk = [&](int kc, int slot) {
        uint32_t st = sbase + (uint32_t)slot * STGB;
#pragma unroll
        for (int i = 0; i < 12; i++) {
            int idx = tid + (i << 8);             // 0..3071
            int isB = idx >= 1024;
            int r = (isB ? (idx - 1024) : idx) >> 3;
            int seg = idx & 7;
            uint32_t dst = st + (isB ? 16384u : 0u) + (uint32_t)(r << 7)
                         + (uint32_t)(((seg ^ (r & 7)) << 4));
            const char* src = (isB ? Bg : Ag) + (size_t)r * (KD * 2) + (size_t)kc * 128 + (seg << 4);
            cpa16(dst, src);
        }
        cpa_commit();
    };

    const int g = lane >> 3, lr = lane & 7;

    auto compute = [&](int slot) {
        uint32_t Abase = sbase + (uint32_t)slot * STGB;
        uint32_t Bbase = Abase + 16384u;
#pragma unroll
        for (int ks = 0; ks < 4; ks++) {
            uint32_t afr[4][4];
#pragma unroll
            for (int mt = 0; mt < 4; mt++) {
                int row = wm * 64 + mt * 16 + (g & 1) * 8 + lr;
                int kseg = ks * 2 + (g >> 1);
                uint32_t addr = Abase + (uint32_t)(row << 7) + (uint32_t)(((kseg ^ (row & 7)) << 4));
                LDMX4(afr[mt], addr);
            }
            uint32_t bfr[4][4];
#pragma unroll
            for (int np = 0; np < 4; np++) {
                int row = wn * 64 + np * 16 + (g >> 1) * 8 + lr;
                int kseg = ks * 2 + (g & 1);
                uint32_t addr = Bbase + (uint32_t)(row << 7) + (uint32_t)(((kseg ^ (row & 7)) << 4));
                LDMX4(bfr[np], addr);
            }
#pragma unroll
            for (int mt = 0; mt < 4; mt++)
#pragma unroll
                for (int nt = 0; nt < 8; nt++) {
                    const uint32_t* bp = &bfr[nt >> 1][(nt & 1) * 2];
                    mma16816(acc[mt][nt], afr[mt], bp[0], bp[1]);
                }
        }
    };

    load_chunk(0, 0);
    load_chunk(1, 1);
    for (int i = 0; i < NCHK; i++) {
        if (i + 1 < NCHK) cpa_wait<1>(); else cpa_wait<0>();
        __syncthreads();
        if (i + 2 < NCHK) load_chunk(i + 2, (i + 2) % 3);
        compute(i % 3);
    }

    const int quad = lane >> 2, tq = lane & 3;
#pragma unroll
    for (int mt = 0; mt < 4; mt++) {
        int mr0 = m0 + wm * 64 + mt * 16 + quad;
#pragma unroll
        for (int half = 0; half < 2; half++) {
            int m = mr0 + half * 8;
            if (m >= TD * BATCH) continue;
            int bb = m & 63, tt = m >> 6;
            float* orow = out + ((size_t)bb * TLEN + (tt + 1)) * VCAB;
#pragma unroll
            for (int nt = 0; nt < 8; nt++) {
                int n = n0 + wn * 64 + nt * 8 + tq * 2;
                float v0 = acc[mt][nt][half * 2 + 0];
                float v1 = acc[mt][nt][half * 2 + 1];
                if (n < VCAB)     orow[n]     = v0 + fc_b[n];
                if (n + 1 < VCAB) orow[n + 1] = v1 + fc_b[n + 1];
            }
        }
    }
}

// ---------------- fp32 SGEMM for encWe: C = enc_out @ attn_W[:,H:]^T + attn_b ----------------
__global__ void sgemm_encWe(const float* __restrict__ Bp, const float* __restrict__ biasp) {
    const float* A = g_encout;
    float* C = g_encWe;

    __shared__ __align__(16) float As[16][64];
    __shared__ __align__(16) float Bs[16][64];

    const int tid = threadIdx.x;
    const int tx = tid & 15, ty = tid >> 4;
    const int m0 = blockIdx.y * 64, n0 = blockIdx.x * 64;
    const int lr = tid >> 2;
    const int lk = (tid & 3) << 2;

    float acc[4][4];
#pragma unroll
    for (int i = 0; i < 4; i++)
#pragma unroll
        for (int j = 0; j < 4; j++) acc[i][j] = 0.0f;

    const float* Arow = A + (size_t)(m0 + lr) * HDIM;
    const float* Brow = Bp + (size_t)(n0 + lr) * (2 * HDIM);

    for (int k0 = 0; k0 < HDIM; k0 += 16) {
        float4 av = *reinterpret_cast<const float4*>(Arow + k0 + lk);
        float4 bv = *reinterpret_cast<const float4*>(Brow + k0 + lk);
        __syncthreads();
        As[lk + 0][lr] = av.x; As[lk + 1][lr] = av.y; As[lk + 2][lr] = av.z; As[lk + 3][lr] = av.w;
        Bs[lk + 0][lr] = bv.x; Bs[lk + 1][lr] = bv.y; Bs[lk + 2][lr] = bv.z; Bs[lk + 3][lr] = bv.w;
        __syncthreads();
#pragma unroll
        for (int kk = 0; kk < 16; kk++) {
            float4 a = *reinterpret_cast<const float4*>(&As[kk][ty << 2]);
            float4 b = *reinterpret_cast<const float4*>(&Bs[kk][tx << 2]);
            float ar[4] = {a.x, a.y, a.z, a.w};
            float br[4] = {b.x, b.y, b.z, b.w};
#pragma unroll
            for (int i = 0; i < 4; i++)
#pragma unroll
                for (int j = 0; j < 4; j++) acc[i][j] += ar[i] * br[j];
        }
    }

#pragma unroll
    for (int i = 0; i < 4; i++) {
        int m = m0 + (ty << 2) + i;
#pragma unroll
        for (int j = 0; j < 4; j++) {
            int n = n0 + (tx << 2) + j;
            C[(size_t)m * HDIM + n] = acc[i][j] + biasp[n];
        }
    }
}

// ---------------- host driver ----------------
extern "C" void kernel_launch(void* const* d_in, const int* in_sizes, int n_in,
                              void* d_out, int out_size) {
    const int*   src     = (const int*)  d_in[0];
    const int*   trg     = (const int*)  d_in[1];
    const float* enc_emb = (const float*)d_in[2];
    const float* enc_Wih = (const float*)d_in[3];
    const float* enc_Whh = (const float*)d_in[4];
    const float* enc_bih = (const float*)d_in[5];
    const float* enc_bhh = (const float*)d_in[6];
    const float* dec_emb = (const float*)d_in[7];
    const float* dec_Wih = (const float*)d_in[8];
    const float* dec_Whh = (const float*)d_in[9];
    const float* dec_bih = (const float*)d_in[10];
    const float* dec_bhh = (const float*)d_in[11];
    const float* attn_W  = (const float*)d_in[12];
    const float* attn_b  = (const float*)d_in[13];
    const float* v_w     = (const float*)d_in[14];
    const float* fc_W    = (const float*)d_in[15];
    const float* fc_b    = (const float*)d_in[16];
    float* out = (float*)d_out;
    (void)in_sizes; (void)n_in; (void)out_size;

    const int ENC_SMEM = 65536 + 32768 + 64 * 33 * 4;        // 106752
    const int HWH_SMEM = 65536 + 32768;                      // 98304
    const int DEC_SMEM = 131072 + 65536 + 64 * 33 * 4;       // 205056
    const int PROJ_SMEM = 3 * 32768;                         // 98304
    cudaFuncSetAttribute(hgemm_fc, cudaFuncAttributeMaxDynamicSharedMemorySize, 3 * STGB);
    cudaFuncSetAttribute(hgemm_proj, cudaFuncAttributeMaxDynamicSharedMemorySize, PROJ_SMEM);
    cudaFuncSetAttribute(enc_step16, cudaFuncAttributeMaxDynamicSharedMemorySize, ENC_SMEM);
    cudaFuncSetAttribute(dec_hwh16, cudaFuncAttributeMaxDynamicSharedMemorySize, HWH_SMEM);
    cudaFuncSetAttribute(dec_gates16, cudaFuncAttributeMaxDynamicSharedMemorySize, DEC_SMEM);

    // setup
    k_biasI<<<8, 256>>>(enc_bih, enc_bhh, dec_bih, dec_bhh);
    k_w16_enc<<<(int)(((size_t)GDIM * HDIM + 255) / 256), 256>>>(enc_Whh);
    k_w16_dec<<<(int)(((size_t)GDIM * 1024 + 255) / 256), 256>>>(dec_Wih, dec_Whh);
    k_w16_wh<<<(int)(((size_t)HDIM * HDIM + 255) / 256), 256>>>(attn_W);
    k_w16_wih<<<(int)(((size_t)GDIM * EDIM + 255) / 256), 256>>>(enc_Wih, dec_Wih);
    k_gather_enc<<<SLEN * BATCH, EDIM>>>(enc_emb, src);
    k_gather_dec<<<TD * BATCH, EDIM>>>(dec_emb, trg);
    k_zero_out<<<(int)(((size_t)BATCH * VCAB + 255) / 256), 256>>>(out);
    k_zero_state<<<(BATCH * HDIM + 255) / 256, 256>>>();
    k_convB_h<<<(int)(((size_t)VCAB * KD / 4 + 255) / 256), 256>>>(fc_W);

    // fp16 input projections (interleaved output + bias), device-global binding via selector
    hgemm_proj<<<dim3((SLEN * BATCH) / 128, GDIM / 128), 256, PROJ_SMEM>>>(0);
    hgemm_proj<<<dim3(MPAD / 128, GDIM / 128), 256, PROJ_SMEM>>>(1);

    // encoder: ONE fused fp16-mma kernel per step
    for (int t = 0; t < SLEN; t++)
        enc_step16<<<64, 256, ENC_SMEM>>>(t);

    // encWe = enc_out @ attn_W[:, H:]^T + attn_b (fp32)
    sgemm_encWe<<<dim3(HDIM / 64, (BATCH * SLEN) / 64), 256>>>(attn_W + HDIM, attn_b);

    k_init_dec<<<128, 256>>>();

    // decoder: THREE kernels per step
    for (int t = 0; t < TD; t++) {
        dec_hwh16<<<16, 256, HWH_SMEM>>>(t);
        k_attn<<<64, 256>>>(v_w, t);
        dec_gates16<<<64, 256, DEC_SMEM>>>(t);
    }

    // tensor-core fc GEMM (128 x 256 tiles)
    hgemm_fc<<<dim3(MPAD / 128, NPAD / 256), 256, 3 * STGB>>>(fc_b, out);
}